// round 14
// baseline (speedup 1.0000x reference)
#include <cuda_runtime.h>
#include <cuda_fp16.h>
#include <cstdint>
#include <cstddef>

// ---------------------------------------------------------------------------
// CompressedLinear (plain-sm_100 target: mma.sync is the only tensor path).
//   out[4096, 11008] = x_f16[4096,4096] @ (w_f16[11008,4096])^T * scale + bias
//
// R14 = R13 shell (measured best: 913.7us) + epilogue bias-preload:
//  - block 128x128x64, 3-stage cp.async, 8 warps, warp tile 64x32, 2 CTAs/SM
//    (16 warps/SM AND 2 independent pipelines/SM -- both proven necessary)
//  - M-fastest grid (W strip sharing + X residency in L2)
//  - streaming (.cs) output stores
//  - NEW: bias (4 unique float2/thread) preloaded before the mainloop,
//    overlapped with the prologue cp.async fill -- removes 16 dependent
//    L2-latency loads from the per-CTA retirement path.
// ---------------------------------------------------------------------------

namespace {
constexpr int M_DIM = 4096;
constexpr int K_DIM = 4096;
constexpr int N_DIM = 11008;

constexpr int BM = 128;
constexpr int BN = 128;
constexpr int BK = 64;
constexpr int STAGES = 3;
constexpr int NTHREADS = 256;
constexpr int KTILES = K_DIM / BK;                 // 64

constexpr int A_STAGE_BYTES = BM * BK * 2;         // 16 KB
constexpr int B_STAGE_BYTES = BN * BK * 2;         // 16 KB
constexpr int STAGE_BYTES   = A_STAGE_BYTES + B_STAGE_BYTES;   // 32 KB
constexpr int SMEM_BYTES    = STAGES * STAGE_BYTES;            // 96 KB
}

// fp16 scratch (allocation-free rule: __device__ globals)
__device__ __half g_X[(size_t)M_DIM * K_DIM];   // 32 MB [M,K]
__device__ __half g_W[(size_t)N_DIM * K_DIM];   // 90 MB [N,K]

// ---------------------------------------------------------------------------
// Conversion kernels: 4 independent float4/int4 loads per thread (MLP=4,
// the measured-fastest form: 14.3-14.5us convert_x @ ~62% DRAM)
// ---------------------------------------------------------------------------
__global__ void convert_x_kernel(const float* __restrict__ x) {
    size_t blk = (size_t)blockIdx.x * 4096;
    #pragma unroll
    for (int t = 0; t < 4; ++t) {
        size_t i = blk + (size_t)t * 1024 + threadIdx.x * 4;
        float4 v = *reinterpret_cast<const float4*>(x + i);
        __half2 h0 = __floats2half2_rn(v.x, v.y);
        __half2 h1 = __floats2half2_rn(v.z, v.w);
        uint2 u;
        u.x = reinterpret_cast<uint32_t&>(h0);
        u.y = reinterpret_cast<uint32_t&>(h1);
        *reinterpret_cast<uint2*>(&g_X[i]) = u;
    }
}

__global__ void convert_w_kernel(const int* __restrict__ w) {
    size_t blk = (size_t)blockIdx.x * 4096;
    #pragma unroll
    for (int t = 0; t < 4; ++t) {
        size_t i = blk + (size_t)t * 1024 + threadIdx.x * 4;
        int4 v = *reinterpret_cast<const int4*>(w + i);
        __half2 h0 = __halves2half2(__int2half_rn(v.x), __int2half_rn(v.y));
        __half2 h1 = __halves2half2(__int2half_rn(v.z), __int2half_rn(v.w));
        uint2 u;
        u.x = reinterpret_cast<uint32_t&>(h0);
        u.y = reinterpret_cast<uint32_t&>(h1);
        *reinterpret_cast<uint2*>(&g_W[i]) = u;
    }
}

// ---------------------------------------------------------------------------
// Helpers
// ---------------------------------------------------------------------------
__device__ __forceinline__ uint32_t swz128(uint32_t b) {
    return b ^ ((b >> 3) & 0x70);
}
__device__ __forceinline__ void cp_async16(uint32_t dst, const void* src) {
    asm volatile("cp.async.cg.shared.global.L2::256B [%0], [%1], 16;\n"
                 :: "r"(dst), "l"(src));
}
__device__ __forceinline__ void cp_commit() {
    asm volatile("cp.async.commit_group;\n");
}
template <int N>
__device__ __forceinline__ void cp_wait() {
    asm volatile("cp.async.wait_group %0;\n" :: "n"(N));
}
__device__ __forceinline__ void stg_cs_v2(float* p, float a, float b) {
    asm volatile("st.global.cs.v2.f32 [%0], {%1, %2};\n"
                 :: "l"(p), "f"(a), "f"(b) : "memory");
}

// ---------------------------------------------------------------------------
// GEMM kernel: 128x128x64 block, 8 warps (2M x 4N), warp tile 64x32,
// mma.sync.m16n8k16 fp16->fp32, 2 CTAs/SM.
// ---------------------------------------------------------------------------
__global__ __launch_bounds__(NTHREADS, 2)
void gemm_kernel(const float* __restrict__ scale_p,
                 const float* __restrict__ bias,
                 float* __restrict__ out) {
    extern __shared__ __align__(128) char smem_raw[];
    const uint32_t smem_base = (uint32_t)__cvta_generic_to_shared(smem_raw);

    const int tid  = threadIdx.x;
    const int warp = tid >> 5;
    const int lane = tid & 31;
    const int mTile = blockIdx.x;   // M fastest: concurrent CTAs share W in L2
    const int nTile = blockIdx.y;

    const int warp_m = warp & 1;    // 0..1  (64 rows each)
    const int warp_n = warp >> 1;   // 0..3  (32 cols each)

    const int mRow0 = mTile * BM;
    const int nCol0 = nTile * BN;

    float acc[4][4][4];
    #pragma unroll
    for (int i = 0; i < 4; ++i)
        #pragma unroll
        for (int j = 0; j < 4; ++j)
            #pragma unroll
            for (int k = 0; k < 4; ++k)
                acc[i][j][k] = 0.0f;

    // preload epilogue constants (hidden under the prologue cp.async fill)
    const int nBase = nCol0 + warp_n * 32;
    const int cl = (lane & 3) * 2;
    float2 bv[4];
    #pragma unroll
    for (int nt = 0; nt < 4; ++nt)
        bv[nt] = *reinterpret_cast<const float2*>(bias + nBase + nt * 8 + cl);
    const float scl = __ldg(scale_p);

    // stage loader: 1024 16B chunks per operand, 256 threads -> 4 each
    auto load_stage = [&](int s, int kt) {
        const uint32_t aBase = smem_base + s * STAGE_BYTES;
        const uint32_t bBase = aBase + A_STAGE_BYTES;
        const int k0 = kt * BK;
        #pragma unroll
        for (int t = 0; t < 4; ++t) {
            int c   = tid + t * NTHREADS;     // 0..1023
            int row = c >> 3;                 // 0..127
            int col = c & 7;
            uint32_t off = swz128((uint32_t)(row * 128 + col * 16));
            cp_async16(aBase + off,
                       &g_X[(size_t)(mRow0 + row) * K_DIM + k0 + col * 8]);
        }
        #pragma unroll
        for (int t = 0; t < 4; ++t) {
            int c   = tid + t * NTHREADS;
            int row = c >> 3;
            int col = c & 7;
            uint32_t off = swz128((uint32_t)(row * 128 + col * 16));
            cp_async16(bBase + off,
                       &g_W[(size_t)(nCol0 + row) * K_DIM + k0 + col * 8]);
        }
    };

    // compute one K-tile from stage s
    auto mma_stage = [&](int s) {
        const uint32_t aBase = smem_base + s * STAGE_BYTES;
        const uint32_t bBase = aBase + A_STAGE_BYTES;
        #pragma unroll
        for (int ks = 0; ks < BK / 16; ++ks) {
            uint32_t af[4][4];
            uint32_t bf[4][2];
            #pragma unroll
            for (int mt = 0; mt < 4; ++mt) {
                int r = warp_m * 64 + mt * 16 + (lane & 15);
                uint32_t addr = aBase +
                    swz128((uint32_t)(r * 128 + ks * 32 + (lane >> 4) * 16));
                asm volatile(
                    "ldmatrix.sync.aligned.m8n8.x4.shared.b16 {%0,%1,%2,%3}, [%4];\n"
                    : "=r"(af[mt][0]), "=r"(af[mt][1]),
                      "=r"(af[mt][2]), "=r"(af[mt][3])
                    : "r"(addr));
            }
            #pragma unroll
            for (int p = 0; p < 2; ++p) {
                int n  = warp_n * 32 + p * 16 + (lane & 7) + ((lane >> 4) << 3);
                int kc = (lane >> 3) & 1;
                uint32_t addr = bBase +
                    swz128((uint32_t)(n * 128 + ks * 32 + kc * 16));
                asm volatile(
                    "ldmatrix.sync.aligned.m8n8.x4.shared.b16 {%0,%1,%2,%3}, [%4];\n"
                    : "=r"(bf[2 * p][0]), "=r"(bf[2 * p][1]),
                      "=r"(bf[2 * p + 1][0]), "=r"(bf[2 * p + 1][1])
                    : "r"(addr));
            }
            #pragma unroll
            for (int mt = 0; mt < 4; ++mt) {
                #pragma unroll
                for (int nt = 0; nt < 4; ++nt) {
                    asm volatile(
                        "mma.sync.aligned.m16n8k16.row.col.f32.f16.f16.f32 "
                        "{%0,%1,%2,%3}, {%4,%5,%6,%7}, {%8,%9}, {%0,%1,%2,%3};\n"
                        : "+f"(acc[mt][nt][0]), "+f"(acc[mt][nt][1]),
                          "+f"(acc[mt][nt][2]), "+f"(acc[mt][nt][3])
                        : "r"(af[mt][0]), "r"(af[mt][1]),
                          "r"(af[mt][2]), "r"(af[mt][3]),
                          "r"(bf[nt][0]), "r"(bf[nt][1]));
                }
            }
        }
    };

    // prologue: fill STAGES-1 stages
    #pragma unroll
    for (int s = 0; s < STAGES - 1; ++s) {
        load_stage(s, s);
        cp_commit();
    }

    // mainloop
    int cs = 0;              // compute stage
    int ps = STAGES - 1;     // prefetch stage
    #pragma unroll 1
    for (int kt = 0; kt < KTILES; ++kt) {
        cp_wait<STAGES - 2>();
        __syncthreads();
        int pf = kt + STAGES - 1;
        if (pf < KTILES) load_stage(ps, pf);
        cp_commit();
        mma_stage(cs);
        if (++cs == STAGES) cs = 0;
        if (++ps == STAGES) ps = 0;
    }

    // epilogue: out = acc*scale + bias (bias already in regs; .cs stores)
    const int mBase = mRow0 + warp_m * 64;
    const int rl = lane >> 2;
    #pragma unroll
    for (int mt = 0; mt < 4; ++mt) {
        #pragma unroll
        for (int nt = 0; nt < 4; ++nt) {
            int c = nBase + nt * 8 + cl;
            int r0 = mBase + mt * 16 + rl;
            stg_cs_v2(out + (size_t)r0 * N_DIM + c,
                      acc[mt][nt][0] * scl + bv[nt].x,
                      acc[mt][nt][1] * scl + bv[nt].y);
            stg_cs_v2(out + (size_t)(r0 + 8) * N_DIM + c,
                      acc[mt][nt][2] * scl + bv[nt].x,
                      acc[mt][nt][3] * scl + bv[nt].y);
        }
    }
}

// ---------------------------------------------------------------------------
// Launch
// ---------------------------------------------------------------------------
extern "C" void kernel_launch(void* const* d_in, const int* in_sizes, int n_in,
                              void* d_out, int out_size) {
    const float* x     = (const float*)d_in[0];
    const int*   w     = (const int*)d_in[1];
    const float* scale = (const float*)d_in[2];
    const float* bias  = (const float*)d_in[3];
    float* out = (float*)d_out;

    cudaFuncSetAttribute(gemm_kernel,
                         cudaFuncAttributeMaxDynamicSharedMemorySize,
                         SMEM_BYTES);

    // x: 16,777,216 / 4096 = 4096 blocks (exact)
    convert_x_kernel<<<4096, 256>>>(x);
    // w: 45,088,768 / 4096 = 11008 blocks (exact)
    convert_w_kernel<<<11008, 256>>>(w);

    dim3 grid(M_DIM / BM, N_DIM / BN);   // (32, 86) -- M fastest
    gemm_kernel<<<grid, NTHREADS, SMEM_BYTES>>>(scale, bias, out);
}

// round 15
// speedup vs baseline: 1.0583x; 1.0583x over previous
#include <cuda_runtime.h>
#include <cuda_fp16.h>
#include <cstdint>
#include <cstddef>

// ---------------------------------------------------------------------------
// CompressedLinear (plain-sm_100 target: mma.sync is the only tensor path).
//   out[4096, 11008] = x_f16[4096,4096] @ (w_f16[11008,4096])^T * scale + bias
//
// R15 = exact revert to R13, the measured optimum (913.7us).
// R14's bias-preload (+9 mainloop-live regs) regressed -51us: the kernel
// sits exactly at the 128-reg ceiling of __launch_bounds__(256,2).
//
// Final configuration (each element experimentally validated):
//  - fp16 scratch GEMM (int8 codes exact in fp16; rel_err 2.1e-4)
//  - block 128x128x64, 3-stage cp.async, 8 warps, warp tile 64x32
//  - 2 CTAs/SM = 16 warps/SM AND two independent pipelines (R6/R7/R8/R9)
//  - M-fastest grid (W strip sharing + X L2 residency)
//  - .cs streaming output stores (R12)
//  - MLP=4 conversion kernels (R12's MLP=8 regressed)
//  - .L2::256B prefetch hint on cp.async (R13)
// ---------------------------------------------------------------------------

namespace {
constexpr int M_DIM = 4096;
constexpr int K_DIM = 4096;
constexpr int N_DIM = 11008;

constexpr int BM = 128;
constexpr int BN = 128;
constexpr int BK = 64;
constexpr int STAGES = 3;
constexpr int NTHREADS = 256;
constexpr int KTILES = K_DIM / BK;                 // 64

constexpr int A_STAGE_BYTES = BM * BK * 2;         // 16 KB
constexpr int B_STAGE_BYTES = BN * BK * 2;         // 16 KB
constexpr int STAGE_BYTES   = A_STAGE_BYTES + B_STAGE_BYTES;   // 32 KB
constexpr int SMEM_BYTES    = STAGES * STAGE_BYTES;            // 96 KB
}

// fp16 scratch (allocation-free rule: __device__ globals)
__device__ __half g_X[(size_t)M_DIM * K_DIM];   // 32 MB [M,K]
__device__ __half g_W[(size_t)N_DIM * K_DIM];   // 90 MB [N,K]

// ---------------------------------------------------------------------------
// Conversion kernels: 4 independent float4/int4 loads per thread (MLP=4,
// the measured-fastest form: 14.3-14.5us convert_x @ ~62% DRAM)
// ---------------------------------------------------------------------------
__global__ void convert_x_kernel(const float* __restrict__ x) {
    size_t blk = (size_t)blockIdx.x * 4096;
    #pragma unroll
    for (int t = 0; t < 4; ++t) {
        size_t i = blk + (size_t)t * 1024 + threadIdx.x * 4;
        float4 v = *reinterpret_cast<const float4*>(x + i);
        __half2 h0 = __floats2half2_rn(v.x, v.y);
        __half2 h1 = __floats2half2_rn(v.z, v.w);
        uint2 u;
        u.x = reinterpret_cast<uint32_t&>(h0);
        u.y = reinterpret_cast<uint32_t&>(h1);
        *reinterpret_cast<uint2*>(&g_X[i]) = u;
    }
}

__global__ void convert_w_kernel(const int* __restrict__ w) {
    size_t blk = (size_t)blockIdx.x * 4096;
    #pragma unroll
    for (int t = 0; t < 4; ++t) {
        size_t i = blk + (size_t)t * 1024 + threadIdx.x * 4;
        int4 v = *reinterpret_cast<const int4*>(w + i);
        __half2 h0 = __halves2half2(__int2half_rn(v.x), __int2half_rn(v.y));
        __half2 h1 = __halves2half2(__int2half_rn(v.z), __int2half_rn(v.w));
        uint2 u;
        u.x = reinterpret_cast<uint32_t&>(h0);
        u.y = reinterpret_cast<uint32_t&>(h1);
        *reinterpret_cast<uint2*>(&g_W[i]) = u;
    }
}

// ---------------------------------------------------------------------------
// Helpers
// ---------------------------------------------------------------------------
__device__ __forceinline__ uint32_t swz128(uint32_t b) {
    return b ^ ((b >> 3) & 0x70);
}
__device__ __forceinline__ void cp_async16(uint32_t dst, const void* src) {
    asm volatile("cp.async.cg.shared.global.L2::256B [%0], [%1], 16;\n"
                 :: "r"(dst), "l"(src));
}
__device__ __forceinline__ void cp_commit() {
    asm volatile("cp.async.commit_group;\n");
}
template <int N>
__device__ __forceinline__ void cp_wait() {
    asm volatile("cp.async.wait_group %0;\n" :: "n"(N));
}
__device__ __forceinline__ void stg_cs_v2(float* p, float a, float b) {
    asm volatile("st.global.cs.v2.f32 [%0], {%1, %2};\n"
                 :: "l"(p), "f"(a), "f"(b) : "memory");
}

// ---------------------------------------------------------------------------
// GEMM kernel: 128x128x64 block, 8 warps (2M x 4N), warp tile 64x32,
// mma.sync.m16n8k16 fp16->fp32, 2 CTAs/SM.
// ---------------------------------------------------------------------------
__global__ __launch_bounds__(NTHREADS, 2)
void gemm_kernel(const float* __restrict__ scale_p,
                 const float* __restrict__ bias,
                 float* __restrict__ out) {
    extern __shared__ __align__(128) char smem_raw[];
    const uint32_t smem_base = (uint32_t)__cvta_generic_to_shared(smem_raw);

    const int tid  = threadIdx.x;
    const int warp = tid >> 5;
    const int lane = tid & 31;
    const int mTile = blockIdx.x;   // M fastest: concurrent CTAs share W in L2
    const int nTile = blockIdx.y;

    const int warp_m = warp & 1;    // 0..1  (64 rows each)
    const int warp_n = warp >> 1;   // 0..3  (32 cols each)

    const int mRow0 = mTile * BM;
    const int nCol0 = nTile * BN;

    float acc[4][4][4];
    #pragma unroll
    for (int i = 0; i < 4; ++i)
        #pragma unroll
        for (int j = 0; j < 4; ++j)
            #pragma unroll
            for (int k = 0; k < 4; ++k)
                acc[i][j][k] = 0.0f;

    // stage loader: 1024 16B chunks per operand, 256 threads -> 4 each
    auto load_stage = [&](int s, int kt) {
        const uint32_t aBase = smem_base + s * STAGE_BYTES;
        const uint32_t bBase = aBase + A_STAGE_BYTES;
        const int k0 = kt * BK;
        #pragma unroll
        for (int t = 0; t < 4; ++t) {
            int c   = tid + t * NTHREADS;     // 0..1023
            int row = c >> 3;                 // 0..127
            int col = c & 7;
            uint32_t off = swz128((uint32_t)(row * 128 + col * 16));
            cp_async16(aBase + off,
                       &g_X[(size_t)(mRow0 + row) * K_DIM + k0 + col * 8]);
        }
        #pragma unroll
        for (int t = 0; t < 4; ++t) {
            int c   = tid + t * NTHREADS;
            int row = c >> 3;
            int col = c & 7;
            uint32_t off = swz128((uint32_t)(row * 128 + col * 16));
            cp_async16(bBase + off,
                       &g_W[(size_t)(nCol0 + row) * K_DIM + k0 + col * 8]);
        }
    };

    // compute one K-tile from stage s
    auto mma_stage = [&](int s) {
        const uint32_t aBase = smem_base + s * STAGE_BYTES;
        const uint32_t bBase = aBase + A_STAGE_BYTES;
        #pragma unroll
        for (int ks = 0; ks < BK / 16; ++ks) {
            uint32_t af[4][4];
            uint32_t bf[4][2];
            #pragma unroll
            for (int mt = 0; mt < 4; ++mt) {
                int r = warp_m * 64 + mt * 16 + (lane & 15);
                uint32_t addr = aBase +
                    swz128((uint32_t)(r * 128 + ks * 32 + (lane >> 4) * 16));
                asm volatile(
                    "ldmatrix.sync.aligned.m8n8.x4.shared.b16 {%0,%1,%2,%3}, [%4];\n"
                    : "=r"(af[mt][0]), "=r"(af[mt][1]),
                      "=r"(af[mt][2]), "=r"(af[mt][3])
                    : "r"(addr));
            }
            #pragma unroll
            for (int p = 0; p < 2; ++p) {
                int n  = warp_n * 32 + p * 16 + (lane & 7) + ((lane >> 4) << 3);
                int kc = (lane >> 3) & 1;
                uint32_t addr = bBase +
                    swz128((uint32_t)(n * 128 + ks * 32 + kc * 16));
                asm volatile(
                    "ldmatrix.sync.aligned.m8n8.x4.shared.b16 {%0,%1,%2,%3}, [%4];\n"
                    : "=r"(bf[2 * p][0]), "=r"(bf[2 * p][1]),
                      "=r"(bf[2 * p + 1][0]), "=r"(bf[2 * p + 1][1])
                    : "r"(addr));
            }
            #pragma unroll
            for (int mt = 0; mt < 4; ++mt) {
                #pragma unroll
                for (int nt = 0; nt < 4; ++nt) {
                    asm volatile(
                        "mma.sync.aligned.m16n8k16.row.col.f32.f16.f16.f32 "
                        "{%0,%1,%2,%3}, {%4,%5,%6,%7}, {%8,%9}, {%0,%1,%2,%3};\n"
                        : "+f"(acc[mt][nt][0]), "+f"(acc[mt][nt][1]),
                          "+f"(acc[mt][nt][2]), "+f"(acc[mt][nt][3])
                        : "r"(af[mt][0]), "r"(af[mt][1]),
                          "r"(af[mt][2]), "r"(af[mt][3]),
                          "r"(bf[nt][0]), "r"(bf[nt][1]));
                }
            }
        }
    };

    // prologue: fill STAGES-1 stages
    #pragma unroll
    for (int s = 0; s < STAGES - 1; ++s) {
        load_stage(s, s);
        cp_commit();
    }

    // mainloop
    int cs = 0;              // compute stage
    int ps = STAGES - 1;     // prefetch stage
    #pragma unroll 1
    for (int kt = 0; kt < KTILES; ++kt) {
        cp_wait<STAGES - 2>();
        __syncthreads();
        int pf = kt + STAGES - 1;
        if (pf < KTILES) load_stage(ps, pf);
        cp_commit();
        mma_stage(cs);
        if (++cs == STAGES) cs = 0;
        if (++ps == STAGES) ps = 0;
    }

    // epilogue: out = acc*scale + bias (streaming stores: keep W/X in L2)
    const float scl = __ldg(scale_p);
    const int mBase = mRow0 + warp_m * 64;
    const int nBase = nCol0 + warp_n * 32;
    const int rl = lane >> 2;
    const int cl = (lane & 3) * 2;
    #pragma unroll
    for (int mt = 0; mt < 4; ++mt) {
        #pragma unroll
        for (int nt = 0; nt < 4; ++nt) {
            int c = nBase + nt * 8 + cl;
            float2 bv = *reinterpret_cast<const float2*>(bias + c);
            int r0 = mBase + mt * 16 + rl;
            stg_cs_v2(out + (size_t)r0 * N_DIM + c,
                      acc[mt][nt][0] * scl + bv.x,
                      acc[mt][nt][1] * scl + bv.y);
            stg_cs_v2(out + (size_t)(r0 + 8) * N_DIM + c,
                      acc[mt][nt][2] * scl + bv.x,
                      acc[mt][nt][3] * scl + bv.y);
        }
    }
}

// ---------------------------------------------------------------------------
// Launch
// ---------------------------------------------------------------------------
extern "C" void kernel_launch(void* const* d_in, const int* in_sizes, int n_in,
                              void* d_out, int out_size) {
    const float* x     = (const float*)d_in[0];
    const int*   w     = (const int*)d_in[1];
    const float* scale = (const float*)d_in[2];
    const float* bias  = (const float*)d_in[3];
    float* out = (float*)d_out;

    cudaFuncSetAttribute(gemm_kernel,
                         cudaFuncAttributeMaxDynamicSharedMemorySize,
                         SMEM_BYTES);

    // x: 16,777,216 / 4096 = 4096 blocks (exact)
    convert_x_kernel<<<4096, 256>>>(x);
    // w: 45,088,768 / 4096 = 11008 blocks (exact)
    convert_w_kernel<<<11008, 256>>>(w);

    dim3 grid(M_DIM / BM, N_DIM / BN);   // (32, 86) -- M fastest
    gemm_kernel<<<grid, NTHREADS, SMEM_BYTES>>>(scale, bias, out);
}